// round 2
// baseline (speedup 1.0000x reference)
#include <cuda_runtime.h>
#include <cuda_bf16.h>
#include <math_constants.h>

// Problem shape (fixed): B=16, T=2048, C=512, H=64
#define BATCH 16
#define SEQ   2048
#define CDIM  512
#define HDIM  64
#define END_TOKEN 32000

#define ROWS_TOTAL (BATCH * SEQ)          // 32768
#define SCALE 0.04419417382415922f        // 512^-0.5

// Scratch (allocation-free rule: __device__ globals)
__device__ float g_q[ROWS_TOTAL * HDIM];
__device__ float g_k[ROWS_TOTAL * HDIM];
__device__ float g_v[ROWS_TOTAL * HDIM];
__device__ int   g_limit[BATCH];

// ---------------------------------------------------------------------------
// Kernel 1: QKV projection.  [32768,512] @ [512,64] x3.
// Block: 32 rows, 256 threads. Thread t owns output col c=t%64 for all three
// matrices, rows rg*8..rg*8+7 (rg=t/64). K staged in 32-wide chunks.
// ---------------------------------------------------------------------------
__global__ __launch_bounds__(256) void proj_kernel(
    const float* __restrict__ x,
    const float* __restrict__ Wk,
    const float* __restrict__ Wq,
    const float* __restrict__ Wv)
{
    __shared__ float xs[32][36];    // 32 rows x 32 k, padded
    __shared__ float ws[32][192];   // k-chunk of [Wq|Wk|Wv]

    const int t    = threadIdx.x;
    const int row0 = blockIdx.x * 32;
    const int c    = t & 63;
    const int rg   = t >> 6;

    float aq[8], ak[8], av[8];
#pragma unroll
    for (int i = 0; i < 8; i++) { aq[i] = 0.f; ak[i] = 0.f; av[i] = 0.f; }

    for (int k0 = 0; k0 < CDIM; k0 += 32) {
        // stage x chunk: 32x32 floats, one float4 per thread
        {
            int r = t >> 3, f = (t & 7) * 4;
            float4 v4 = *reinterpret_cast<const float4*>(
                x + (size_t)(row0 + r) * CDIM + k0 + f);
            *reinterpret_cast<float4*>(&xs[r][f]) = v4;
        }
        // stage W chunk: 32x192 floats = 1536 float4, 6 per thread
#pragma unroll
        for (int it = 0; it < 6; it++) {
            int idx = t + 256 * it;
            int kk  = idx / 48;
            int f   = idx % 48;
            int mat = f >> 4;
            int c4  = (f & 15) * 4;
            const float* Wm = (mat == 0) ? Wq : (mat == 1) ? Wk : Wv;
            float4 v4 = *reinterpret_cast<const float4*>(
                Wm + (size_t)(k0 + kk) * HDIM + c4);
            *reinterpret_cast<float4*>(&ws[kk][mat * 64 + c4]) = v4;
        }
        __syncthreads();

#pragma unroll
        for (int kk = 0; kk < 32; kk++) {
            float wq = ws[kk][c];
            float wk = ws[kk][64 + c];
            float wv = ws[kk][128 + c];
#pragma unroll
            for (int i = 0; i < 8; i++) {
                float xx = xs[rg * 8 + i][kk];
                aq[i] = fmaf(xx, wq, aq[i]);
                ak[i] = fmaf(xx, wk, ak[i]);
                av[i] = fmaf(xx, wv, av[i]);
            }
        }
        __syncthreads();
    }

#pragma unroll
    for (int i = 0; i < 8; i++) {
        size_t o = (size_t)(row0 + rg * 8 + i) * HDIM + c;
        g_q[o] = aq[i];
        g_k[o] = ak[i];
        g_v[o] = av[i];
    }
}

// ---------------------------------------------------------------------------
// Kernel 2: end-token scan per batch (never fires for this dataset, but
// faithful to the reference semantics).
// ---------------------------------------------------------------------------
__global__ void limit_kernel(const int* __restrict__ idx)
{
    __shared__ int best;
    if (threadIdx.x == 0) best = SEQ;
    __syncthreads();
    const int b = blockIdx.x;
    for (int t = threadIdx.x; t < SEQ; t += blockDim.x)
        if (idx[(size_t)b * SEQ + t] == END_TOKEN) atomicMin(&best, t);
    __syncthreads();
    if (threadIdx.x == 0) g_limit[b] = best;
}

// ---------------------------------------------------------------------------
// Kernel 3: causal flash attention, fp32.
// Block = (b, q-tile of 64). 256 threads, 4x4 register micro-tiles.
// smem: Qs[64][68] (q-major), KT[64][68] (h-major K, reused for P[q][k]),
//       Vs[64][68] (k-major). 52224 B dynamic smem.
// ---------------------------------------------------------------------------
#define TPAD 68
#define ATTN_SMEM_BYTES (3 * 64 * TPAD * 4)

__global__ __launch_bounds__(256) void attn_kernel(float* __restrict__ out)
{
    extern __shared__ float sm[];
    float* Qs = sm;                 // [64][TPAD], [q][h]
    float* KT = sm + 64 * TPAD;     // [64][TPAD], [h][k]; later P as [q][k]
    float* Vs = sm + 2 * 64 * TPAD; // [64][TPAD], [k][h]

    const int t  = threadIdx.x;
    const int tx = t & 15;          // k / h column group
    const int ty = t >> 4;          // q row group
    const int b  = blockIdx.y;
    const int qt = (gridDim.x - 1) - blockIdx.x;  // heavy tiles first
    const int q0 = qt * 64;
    const size_t baseQ = ((size_t)b * SEQ + q0) * HDIM;

    // load Q tile
#pragma unroll
    for (int it = 0; it < 4; it++) {
        int idx = t + 256 * it;
        int r = idx >> 4, f = (idx & 15) * 4;
        *reinterpret_cast<float4*>(&Qs[r * TPAD + f]) =
            *reinterpret_cast<const float4*>(&g_q[baseQ + (size_t)r * HDIM + f]);
    }

    float m[4], l[4], o[4][4];
#pragma unroll
    for (int i = 0; i < 4; i++) {
        m[i] = -CUDART_INF_F;
        l[i] = 0.f;
#pragma unroll
        for (int j = 0; j < 4; j++) o[i][j] = 0.f;
    }

    for (int kt = 0; kt <= qt; kt++) {
        __syncthreads();  // prior-iter smem reads done (also covers Q load)
        const size_t baseK = ((size_t)b * SEQ + kt * 64) * HDIM;
#pragma unroll
        for (int it = 0; it < 4; it++) {
            int idx = t + 256 * it;
            int r = idx >> 4, f = (idx & 15) * 4;
            float4 kv = *reinterpret_cast<const float4*>(
                &g_k[baseK + (size_t)r * HDIM + f]);
            KT[(f + 0) * TPAD + r] = kv.x;   // transpose to [h][k]
            KT[(f + 1) * TPAD + r] = kv.y;
            KT[(f + 2) * TPAD + r] = kv.z;
            KT[(f + 3) * TPAD + r] = kv.w;
            *reinterpret_cast<float4*>(&Vs[r * TPAD + f]) =
                *reinterpret_cast<const float4*>(&g_v[baseK + (size_t)r * HDIM + f]);
        }
        __syncthreads();

        // ---- S = Q K^T (4x4 micro-tile) ----
        float s[4][4];
#pragma unroll
        for (int i = 0; i < 4; i++)
#pragma unroll
            for (int j = 0; j < 4; j++) s[i][j] = 0.f;

#pragma unroll
        for (int h = 0; h < HDIM; h += 4) {
            float4 qf[4], kf[4];
#pragma unroll
            for (int i = 0; i < 4; i++)
                qf[i] = *reinterpret_cast<const float4*>(&Qs[(ty * 4 + i) * TPAD + h]);
#pragma unroll
            for (int hh = 0; hh < 4; hh++)
                kf[hh] = *reinterpret_cast<const float4*>(&KT[(h + hh) * TPAD + tx * 4]);
#pragma unroll
            for (int hh = 0; hh < 4; hh++) {
                float kx = kf[hh].x, ky = kf[hh].y, kz = kf[hh].z, kw = kf[hh].w;
#pragma unroll
                for (int i = 0; i < 4; i++) {
                    float qv = reinterpret_cast<const float*>(&qf[i])[hh];
                    s[i][0] = fmaf(qv, kx, s[i][0]);
                    s[i][1] = fmaf(qv, ky, s[i][1]);
                    s[i][2] = fmaf(qv, kz, s[i][2]);
                    s[i][3] = fmaf(qv, kw, s[i][3]);
                }
            }
        }

        // ---- scale + causal mask (only the diagonal tile needs it) ----
        const bool diag = (kt == qt);
#pragma unroll
        for (int i = 0; i < 4; i++)
#pragma unroll
            for (int j = 0; j < 4; j++) {
                float v = s[i][j] * SCALE;
                if (diag && (tx * 4 + j) > (ty * 4 + i)) v = -1e30f;
                s[i][j] = v;
            }

        // ---- online softmax update ----
#pragma unroll
        for (int i = 0; i < 4; i++) {
            float rm = fmaxf(fmaxf(s[i][0], s[i][1]), fmaxf(s[i][2], s[i][3]));
#pragma unroll
            for (int d = 8; d > 0; d >>= 1)
                rm = fmaxf(rm, __shfl_xor_sync(0xffffffffu, rm, d));
            float mn = fmaxf(m[i], rm);
            float fc = __expf(m[i] - mn);
            float rs = 0.f;
#pragma unroll
            for (int j = 0; j < 4; j++) {
                float p = __expf(s[i][j] - mn);
                s[i][j] = p;
                rs += p;
            }
#pragma unroll
            for (int d = 8; d > 0; d >>= 1)
                rs += __shfl_xor_sync(0xffffffffu, rs, d);
            l[i] = l[i] * fc + rs;
            m[i] = mn;
#pragma unroll
            for (int j = 0; j < 4; j++) o[i][j] *= fc;
        }

        __syncthreads();  // all KT (K) reads done before overwrite with P
#pragma unroll
        for (int i = 0; i < 4; i++)
            *reinterpret_cast<float4*>(&KT[(ty * 4 + i) * TPAD + tx * 4]) =
                make_float4(s[i][0], s[i][1], s[i][2], s[i][3]);
        __syncthreads();

        // ---- O += P V ----
#pragma unroll
        for (int k = 0; k < 64; k += 4) {
            float4 pf[4], vf[4];
#pragma unroll
            for (int i = 0; i < 4; i++)
                pf[i] = *reinterpret_cast<const float4*>(&KT[(ty * 4 + i) * TPAD + k]);
#pragma unroll
            for (int kk = 0; kk < 4; kk++)
                vf[kk] = *reinterpret_cast<const float4*>(&Vs[(k + kk) * TPAD + tx * 4]);
#pragma unroll
            for (int kk = 0; kk < 4; kk++) {
                float vx = vf[kk].x, vy = vf[kk].y, vz = vf[kk].z, vw = vf[kk].w;
#pragma unroll
                for (int i = 0; i < 4; i++) {
                    float pv = reinterpret_cast<const float*>(&pf[i])[kk];
                    o[i][0] = fmaf(pv, vx, o[i][0]);
                    o[i][1] = fmaf(pv, vy, o[i][1]);
                    o[i][2] = fmaf(pv, vz, o[i][2]);
                    o[i][3] = fmaf(pv, vw, o[i][3]);
                }
            }
        }
    }

    // ---- epilogue: normalize, end-token row mask, store ----
    const int limit = g_limit[b];
    const float qnan = __int_as_float(0x7FC00000);
#pragma unroll
    for (int i = 0; i < 4; i++) {
        int q = q0 + ty * 4 + i;
        float4 r;
        if (q >= limit) {
            r = make_float4(qnan, qnan, qnan, qnan);
        } else {
            float inv = 1.f / l[i];
            r = make_float4(o[i][0] * inv, o[i][1] * inv,
                            o[i][2] * inv, o[i][3] * inv);
        }
        *reinterpret_cast<float4*>(&out[((size_t)b * SEQ + q) * HDIM + tx * 4]) = r;
    }
}

// ---------------------------------------------------------------------------
extern "C" void kernel_launch(void* const* d_in, const int* in_sizes, int n_in,
                              void* d_out, int out_size)
{
    const float* x  = (const float*)d_in[0];
    const float* Wk = (const float*)d_in[1];
    const float* Wq = (const float*)d_in[2];
    const float* Wv = (const float*)d_in[3];
    const int*  idx = (const int*)d_in[4];
    float* out = (float*)d_out;

    (void)in_sizes; (void)n_in; (void)out_size;

    cudaFuncSetAttribute(attn_kernel,
                         cudaFuncAttributeMaxDynamicSharedMemorySize,
                         ATTN_SMEM_BYTES);

    proj_kernel<<<ROWS_TOTAL / 32, 256>>>(x, Wk, Wq, Wv);
    limit_kernel<<<BATCH, 256>>>(idx);
    attn_kernel<<<dim3(SEQ / 64, BATCH), 256, ATTN_SMEM_BYTES>>>(out);
}

// round 3
// speedup vs baseline: 1.0017x; 1.0017x over previous
#include <cuda_runtime.h>
#include <cuda_bf16.h>
#include <math_constants.h>

// Problem shape (fixed): B=16, T=2048, C=512, H=64
#define BATCH 16
#define SEQ   2048
#define CDIM  512
#define HDIM  64
#define END_TOKEN 32000

#define ROWS_TOTAL (BATCH * SEQ)          // 32768
#define SCALE 0.04419417382415922f        // 512^-0.5

// Scratch (allocation-free rule: __device__ globals)
__device__ float g_q[ROWS_TOTAL * HDIM];
__device__ float g_k[ROWS_TOTAL * HDIM];
__device__ float g_v[ROWS_TOTAL * HDIM];
__device__ int   g_limit[BATCH];

// ---------------------------------------------------------------------------
// Kernel 1: QKV projection.  [32768,512] @ [512,64] x3.
// Block: 32 rows, 256 threads. Thread t owns output col c=t%64 for all three
// matrices, rows rg*8..rg*8+7 (rg=t/64). K staged in 32-wide chunks.
// ---------------------------------------------------------------------------
__global__ __launch_bounds__(256) void proj_kernel(
    const float* __restrict__ x,
    const float* __restrict__ Wk,
    const float* __restrict__ Wq,
    const float* __restrict__ Wv)
{
    __shared__ float xs[32][36];    // 32 rows x 32 k, padded
    __shared__ float ws[32][192];   // k-chunk of [Wq|Wk|Wv]

    const int t    = threadIdx.x;
    const int row0 = blockIdx.x * 32;
    const int c    = t & 63;
    const int rg   = t >> 6;

    float aq[8], ak[8], av[8];
#pragma unroll
    for (int i = 0; i < 8; i++) { aq[i] = 0.f; ak[i] = 0.f; av[i] = 0.f; }

    for (int k0 = 0; k0 < CDIM; k0 += 32) {
        // stage x chunk: 32x32 floats, one float4 per thread
        {
            int r = t >> 3, f = (t & 7) * 4;
            float4 v4 = *reinterpret_cast<const float4*>(
                x + (size_t)(row0 + r) * CDIM + k0 + f);
            *reinterpret_cast<float4*>(&xs[r][f]) = v4;
        }
        // stage W chunk: 32x192 floats = 1536 float4, 6 per thread
#pragma unroll
        for (int it = 0; it < 6; it++) {
            int idx = t + 256 * it;
            int kk  = idx / 48;
            int f   = idx % 48;
            int mat = f >> 4;
            int c4  = (f & 15) * 4;
            const float* Wm = (mat == 0) ? Wq : (mat == 1) ? Wk : Wv;
            float4 v4 = *reinterpret_cast<const float4*>(
                Wm + (size_t)(k0 + kk) * HDIM + c4);
            *reinterpret_cast<float4*>(&ws[kk][mat * 64 + c4]) = v4;
        }
        __syncthreads();

#pragma unroll
        for (int kk = 0; kk < 32; kk++) {
            float wq = ws[kk][c];
            float wk = ws[kk][64 + c];
            float wv = ws[kk][128 + c];
#pragma unroll
            for (int i = 0; i < 8; i++) {
                float xx = xs[rg * 8 + i][kk];
                aq[i] = fmaf(xx, wq, aq[i]);
                ak[i] = fmaf(xx, wk, ak[i]);
                av[i] = fmaf(xx, wv, av[i]);
            }
        }
        __syncthreads();
    }

#pragma unroll
    for (int i = 0; i < 8; i++) {
        size_t o = (size_t)(row0 + rg * 8 + i) * HDIM + c;
        g_q[o] = aq[i];
        g_k[o] = ak[i];
        g_v[o] = av[i];
    }
}

// ---------------------------------------------------------------------------
// Kernel 2: end-token scan per batch (never fires for this dataset, but
// faithful to the reference semantics).
// ---------------------------------------------------------------------------
__global__ void limit_kernel(const int* __restrict__ idx)
{
    __shared__ int best;
    if (threadIdx.x == 0) best = SEQ;
    __syncthreads();
    const int b = blockIdx.x;
    for (int t = threadIdx.x; t < SEQ; t += blockDim.x)
        if (idx[(size_t)b * SEQ + t] == END_TOKEN) atomicMin(&best, t);
    __syncthreads();
    if (threadIdx.x == 0) g_limit[b] = best;
}

// ---------------------------------------------------------------------------
// Kernel 3: causal flash attention, fp32.
// Block = (b, q-tile of 64). 256 threads, 4x4 register micro-tiles.
// smem: Qs[64][68] (q-major), KT[64][68] (h-major K, reused for P[q][k]),
//       Vs[64][68] (k-major). 52224 B dynamic smem.
// ---------------------------------------------------------------------------
#define TPAD 68
#define ATTN_SMEM_BYTES (3 * 64 * TPAD * 4)

__global__ __launch_bounds__(256) void attn_kernel(float* __restrict__ out)
{
    extern __shared__ float sm[];
    float* Qs = sm;                 // [64][TPAD], [q][h]
    float* KT = sm + 64 * TPAD;     // [64][TPAD], [h][k]; later P as [q][k]
    float* Vs = sm + 2 * 64 * TPAD; // [64][TPAD], [k][h]

    const int t  = threadIdx.x;
    const int tx = t & 15;          // k / h column group
    const int ty = t >> 4;          // q row group
    const int b  = blockIdx.y;
    const int qt = (gridDim.x - 1) - blockIdx.x;  // heavy tiles first
    const int q0 = qt * 64;
    const size_t baseQ = ((size_t)b * SEQ + q0) * HDIM;

    // load Q tile
#pragma unroll
    for (int it = 0; it < 4; it++) {
        int idx = t + 256 * it;
        int r = idx >> 4, f = (idx & 15) * 4;
        *reinterpret_cast<float4*>(&Qs[r * TPAD + f]) =
            *reinterpret_cast<const float4*>(&g_q[baseQ + (size_t)r * HDIM + f]);
    }

    float m[4], l[4], o[4][4];
#pragma unroll
    for (int i = 0; i < 4; i++) {
        m[i] = -CUDART_INF_F;
        l[i] = 0.f;
#pragma unroll
        for (int j = 0; j < 4; j++) o[i][j] = 0.f;
    }

    for (int kt = 0; kt <= qt; kt++) {
        __syncthreads();  // prior-iter smem reads done (also covers Q load)
        const size_t baseK = ((size_t)b * SEQ + kt * 64) * HDIM;
#pragma unroll
        for (int it = 0; it < 4; it++) {
            int idx = t + 256 * it;
            int r = idx >> 4, f = (idx & 15) * 4;
            float4 kv = *reinterpret_cast<const float4*>(
                &g_k[baseK + (size_t)r * HDIM + f]);
            KT[(f + 0) * TPAD + r] = kv.x;   // transpose to [h][k]
            KT[(f + 1) * TPAD + r] = kv.y;
            KT[(f + 2) * TPAD + r] = kv.z;
            KT[(f + 3) * TPAD + r] = kv.w;
            *reinterpret_cast<float4*>(&Vs[r * TPAD + f]) =
                *reinterpret_cast<const float4*>(&g_v[baseK + (size_t)r * HDIM + f]);
        }
        __syncthreads();

        // ---- S = Q K^T (4x4 micro-tile) ----
        float s[4][4];
#pragma unroll
        for (int i = 0; i < 4; i++)
#pragma unroll
            for (int j = 0; j < 4; j++) s[i][j] = 0.f;

#pragma unroll
        for (int h = 0; h < HDIM; h += 4) {
            float4 qf[4], kf[4];
#pragma unroll
            for (int i = 0; i < 4; i++)
                qf[i] = *reinterpret_cast<const float4*>(&Qs[(ty * 4 + i) * TPAD + h]);
#pragma unroll
            for (int hh = 0; hh < 4; hh++)
                kf[hh] = *reinterpret_cast<const float4*>(&KT[(h + hh) * TPAD + tx * 4]);
#pragma unroll
            for (int hh = 0; hh < 4; hh++) {
                float kx = kf[hh].x, ky = kf[hh].y, kz = kf[hh].z, kw = kf[hh].w;
#pragma unroll
                for (int i = 0; i < 4; i++) {
                    float qv = reinterpret_cast<const float*>(&qf[i])[hh];
                    s[i][0] = fmaf(qv, kx, s[i][0]);
                    s[i][1] = fmaf(qv, ky, s[i][1]);
                    s[i][2] = fmaf(qv, kz, s[i][2]);
                    s[i][3] = fmaf(qv, kw, s[i][3]);
                }
            }
        }

        // ---- scale + causal mask (only the diagonal tile needs it) ----
        const bool diag = (kt == qt);
#pragma unroll
        for (int i = 0; i < 4; i++)
#pragma unroll
            for (int j = 0; j < 4; j++) {
                float v = s[i][j] * SCALE;
                if (diag && (tx * 4 + j) > (ty * 4 + i)) v = -1e30f;
                s[i][j] = v;
            }

        // ---- online softmax update ----
#pragma unroll
        for (int i = 0; i < 4; i++) {
            float rm = fmaxf(fmaxf(s[i][0], s[i][1]), fmaxf(s[i][2], s[i][3]));
#pragma unroll
            for (int d = 8; d > 0; d >>= 1)
                rm = fmaxf(rm, __shfl_xor_sync(0xffffffffu, rm, d));
            float mn = fmaxf(m[i], rm);
            float fc = __expf(m[i] - mn);
            float rs = 0.f;
#pragma unroll
            for (int j = 0; j < 4; j++) {
                float p = __expf(s[i][j] - mn);
                s[i][j] = p;
                rs += p;
            }
#pragma unroll
            for (int d = 8; d > 0; d >>= 1)
                rs += __shfl_xor_sync(0xffffffffu, rs, d);
            l[i] = l[i] * fc + rs;
            m[i] = mn;
#pragma unroll
            for (int j = 0; j < 4; j++) o[i][j] *= fc;
        }

        __syncthreads();  // all KT (K) reads done before overwrite with P
#pragma unroll
        for (int i = 0; i < 4; i++)
            *reinterpret_cast<float4*>(&KT[(ty * 4 + i) * TPAD + tx * 4]) =
                make_float4(s[i][0], s[i][1], s[i][2], s[i][3]);
        __syncthreads();

        // ---- O += P V ----
#pragma unroll
        for (int k = 0; k < 64; k += 4) {
            float4 pf[4], vf[4];
#pragma unroll
            for (int i = 0; i < 4; i++)
                pf[i] = *reinterpret_cast<const float4*>(&KT[(ty * 4 + i) * TPAD + k]);
#pragma unroll
            for (int kk = 0; kk < 4; kk++)
                vf[kk] = *reinterpret_cast<const float4*>(&Vs[(k + kk) * TPAD + tx * 4]);
#pragma unroll
            for (int kk = 0; kk < 4; kk++) {
                float vx = vf[kk].x, vy = vf[kk].y, vz = vf[kk].z, vw = vf[kk].w;
#pragma unroll
                for (int i = 0; i < 4; i++) {
                    float pv = reinterpret_cast<const float*>(&pf[i])[kk];
                    o[i][0] = fmaf(pv, vx, o[i][0]);
                    o[i][1] = fmaf(pv, vy, o[i][1]);
                    o[i][2] = fmaf(pv, vz, o[i][2]);
                    o[i][3] = fmaf(pv, vw, o[i][3]);
                }
            }
        }
    }

    // ---- epilogue: normalize, end-token row mask, store ----
    const int limit = g_limit[b];
    const float qnan = __int_as_float(0x7FC00000);
#pragma unroll
    for (int i = 0; i < 4; i++) {
        int q = q0 + ty * 4 + i;
        float4 r;
        if (q >= limit) {
            r = make_float4(qnan, qnan, qnan, qnan);
        } else {
            float inv = 1.f / l[i];
            r = make_float4(o[i][0] * inv, o[i][1] * inv,
                            o[i][2] * inv, o[i][3] * inv);
        }
        *reinterpret_cast<float4*>(&out[((size_t)b * SEQ + q) * HDIM + tx * 4]) = r;
    }
}

// ---------------------------------------------------------------------------
extern "C" void kernel_launch(void* const* d_in, const int* in_sizes, int n_in,
                              void* d_out, int out_size)
{
    const float* x  = (const float*)d_in[0];
    const float* Wk = (const float*)d_in[1];
    const float* Wq = (const float*)d_in[2];
    const float* Wv = (const float*)d_in[3];
    const int*  idx = (const int*)d_in[4];
    float* out = (float*)d_out;

    (void)in_sizes; (void)n_in; (void)out_size;

    cudaFuncSetAttribute(attn_kernel,
                         cudaFuncAttributeMaxDynamicSharedMemorySize,
                         ATTN_SMEM_BYTES);

    proj_kernel<<<ROWS_TOTAL / 32, 256>>>(x, Wk, Wq, Wv);
    limit_kernel<<<BATCH, 256>>>(idx);
    attn_kernel<<<dim3(SEQ / 64, BATCH), 256, ATTN_SMEM_BYTES>>>(out);
}

// round 4
// speedup vs baseline: 1.0222x; 1.0205x over previous
#include <cuda_runtime.h>
#include <cuda_bf16.h>
#include <math_constants.h>

// Problem shape (fixed): B=16, T=2048, C=512, H=64
#define BATCH 16
#define SEQ   2048
#define CDIM  512
#define HDIM  64
#define END_TOKEN 32000

#define ROWS_TOTAL (BATCH * SEQ)          // 32768
#define SCALE 0.04419417382415922f        // 512^-0.5

typedef unsigned long long ull;

// ---- packed fp32x2 helpers (PTX-only instructions on sm_103a) ----
__device__ __forceinline__ ull ffma2(ull a, ull b, ull c) {
    ull d; asm("fma.rn.f32x2 %0,%1,%2,%3;" : "=l"(d) : "l"(a), "l"(b), "l"(c));
    return d;
}
__device__ __forceinline__ ull fmul2(ull a, ull b) {
    ull d; asm("mul.rn.f32x2 %0,%1,%2;" : "=l"(d) : "l"(a), "l"(b));
    return d;
}
__device__ __forceinline__ ull pack2(float lo, float hi) {
    ull d; asm("mov.b64 %0,{%1,%2};" : "=l"(d) : "f"(lo), "f"(hi));
    return d;
}
__device__ __forceinline__ ull dup2(float v) { return pack2(v, v); }
__device__ __forceinline__ void unpack2(ull d, float& lo, float& hi) {
    asm("mov.b64 {%0,%1},%2;" : "=f"(lo), "=f"(hi) : "l"(d));
}

// Scratch (allocation-free rule: __device__ globals)
__device__ float g_q[ROWS_TOTAL * HDIM];
__device__ float g_k[ROWS_TOTAL * HDIM];
__device__ float g_v[ROWS_TOTAL * HDIM];
__device__ int   g_limit[BATCH];

// ---------------------------------------------------------------------------
// Kernel 1: QKV projection.  [32768,512] @ [512,64] x3, packed fp32x2.
// Block tile: 64 rows x 192 cols (Wq|Wk|Wv). 256 threads:
//   tx = t&31 -> column pair 2tx,2tx+1 in each matrix
//   ty = t>>5 -> rows ty*8 .. ty*8+7 as 4 row-pairs
// x staged transposed [kk][row] so a row-pair is one broadcast LDS.64.
// ---------------------------------------------------------------------------
__global__ __launch_bounds__(256) void proj_kernel(
    const float* __restrict__ x,
    const float* __restrict__ Wk,
    const float* __restrict__ Wq,
    const float* __restrict__ Wv)
{
    __shared__ float xs[32][66];    // [kk][row], 64 rows used
    __shared__ float ws[32][192];   // [kk][Wq|Wk|Wv]

    const int t    = threadIdx.x;
    const int row0 = blockIdx.x * 64;
    const int tx   = t & 31;
    const int ty   = t >> 5;

    ull acc[3][2][4];               // [mat][col half][row pair]
#pragma unroll
    for (int m = 0; m < 3; m++)
#pragma unroll
        for (int h = 0; h < 2; h++)
#pragma unroll
            for (int p = 0; p < 4; p++) acc[m][h][p] = 0ull;

    for (int k0 = 0; k0 < CDIM; k0 += 32) {
        // stage x chunk transposed: 64 rows x 32 kk
        {
            int r = t >> 2, f = (t & 3) * 8;
            const float* xp = x + (size_t)(row0 + r) * CDIM + k0 + f;
            float4 a = *reinterpret_cast<const float4*>(xp);
            float4 b = *reinterpret_cast<const float4*>(xp + 4);
            xs[f + 0][r] = a.x; xs[f + 1][r] = a.y;
            xs[f + 2][r] = a.z; xs[f + 3][r] = a.w;
            xs[f + 4][r] = b.x; xs[f + 5][r] = b.y;
            xs[f + 6][r] = b.z; xs[f + 7][r] = b.w;
        }
        // stage W chunk: 32x192 floats = 1536 float4, 6 per thread
#pragma unroll
        for (int it = 0; it < 6; it++) {
            int idx = t + 256 * it;
            int kk  = idx / 48;
            int f   = idx % 48;
            int mat = f >> 4;
            int c4  = (f & 15) * 4;
            const float* Wm = (mat == 0) ? Wq : (mat == 1) ? Wk : Wv;
            float4 v4 = *reinterpret_cast<const float4*>(
                Wm + (size_t)(k0 + kk) * HDIM + c4);
            *reinterpret_cast<float4*>(&ws[kk][mat * 64 + c4]) = v4;
        }
        __syncthreads();

#pragma unroll
        for (int kk = 0; kk < 32; kk++) {
            ull xp[4];
#pragma unroll
            for (int p = 0; p < 4; p++)
                xp[p] = *reinterpret_cast<const ull*>(&xs[kk][ty * 8 + 2 * p]);
#pragma unroll
            for (int mat = 0; mat < 3; mat++) {
                ull w2 = *reinterpret_cast<const ull*>(&ws[kk][mat * 64 + 2 * tx]);
                float wlo, whi; unpack2(w2, wlo, whi);
                ull dlo = dup2(wlo), dhi = dup2(whi);
#pragma unroll
                for (int p = 0; p < 4; p++) {
                    acc[mat][0][p] = ffma2(xp[p], dlo, acc[mat][0][p]);
                    acc[mat][1][p] = ffma2(xp[p], dhi, acc[mat][1][p]);
                }
            }
        }
        __syncthreads();
    }

    // store: pair halves are consecutive rows, same column
    float* outs[3] = { g_q, g_k, g_v };
#pragma unroll
    for (int mat = 0; mat < 3; mat++) {
        float* g = outs[mat];
#pragma unroll
        for (int h = 0; h < 2; h++) {
            int c = 2 * tx + h;
#pragma unroll
            for (int p = 0; p < 4; p++) {
                float lo, hi; unpack2(acc[mat][h][p], lo, hi);
                size_t r = (size_t)(row0 + ty * 8 + 2 * p);
                g[r * HDIM + c]       = lo;
                g[(r + 1) * HDIM + c] = hi;
            }
        }
    }
}

// ---------------------------------------------------------------------------
// Kernel 2: end-token scan per batch (faithful to reference; never fires here).
// ---------------------------------------------------------------------------
__global__ void limit_kernel(const int* __restrict__ idx)
{
    __shared__ int best;
    if (threadIdx.x == 0) best = SEQ;
    __syncthreads();
    const int b = blockIdx.x;
    for (int t = threadIdx.x; t < SEQ; t += blockDim.x)
        if (idx[(size_t)b * SEQ + t] == END_TOKEN) atomicMin(&best, t);
    __syncthreads();
    if (threadIdx.x == 0) g_limit[b] = best;
}

// ---------------------------------------------------------------------------
// Kernel 3: causal flash attention, fp32 with packed fp32x2 GEMMs.
// Tile: 128 q-rows x 128 k-cols. 256 threads:
//   tx = t&15 -> 8 k-cols (S) / 4 h-cols (PV);  ty = t>>4 -> 8 q-rows
// smem: Qs[128][68], KT[64][132] (K transposed), Vs[128][68], Ps[128][132]
// Total 171,008 B dynamic smem -> 1 CTA/SM.
// ---------------------------------------------------------------------------
#define HP 68
#define KP 132
#define ATTN_SMEM_BYTES ((128*HP + 64*KP + 128*HP + 128*KP) * 4)

__global__ __launch_bounds__(256, 1) void attn_kernel(float* __restrict__ out)
{
    extern __shared__ float sm[];
    float* Qs  = sm;                          // [128][HP]  [q][h]
    float* KTs = Qs  + 128 * HP;              // [64][KP]   [h][k]
    float* Vs  = KTs + 64  * KP;              // [128][HP]  [k][h]
    float* Ps  = Vs  + 128 * HP;              // [128][KP]  [q][k]

    const int t  = threadIdx.x;
    const int tx = t & 15;
    const int ty = t >> 4;
    const int b  = blockIdx.y;
    const int qt = (gridDim.x - 1) - blockIdx.x;   // heavy tiles first
    const int q0 = qt * 128;

    // load Q tile [128][64]
    {
        int r = t >> 1, f0 = (t & 1) * 32;
        const float* qp = g_q + ((size_t)b * SEQ + q0 + r) * HDIM + f0;
#pragma unroll
        for (int it = 0; it < 8; it++)
            *reinterpret_cast<float4*>(&Qs[r * HP + f0 + it * 4]) =
                *reinterpret_cast<const float4*>(qp + it * 4);
    }

    float m[8], l[8];
    ull o2[8][2];                               // 8 q-rows x 2 h-pairs (4 h cols)
#pragma unroll
    for (int i = 0; i < 8; i++) {
        m[i] = -CUDART_INF_F; l[i] = 0.f;
        o2[i][0] = 0ull; o2[i][1] = 0ull;
    }

    for (int kt = 0; kt <= qt; kt++) {
        __syncthreads();   // prior-iter smem reads done (also covers Q load)

        // stage K (transposed) and V: 128 rows x 64
        {
            int r = t >> 1, f0 = (t & 1) * 32;
            const size_t base = ((size_t)b * SEQ + kt * 128 + r) * HDIM + f0;
#pragma unroll
            for (int it = 0; it < 8; it++) {
                float4 kv = *reinterpret_cast<const float4*>(&g_k[base + it * 4]);
                int h = f0 + it * 4;
                KTs[(h + 0) * KP + r] = kv.x;
                KTs[(h + 1) * KP + r] = kv.y;
                KTs[(h + 2) * KP + r] = kv.z;
                KTs[(h + 3) * KP + r] = kv.w;
                *reinterpret_cast<float4*>(&Vs[r * HP + h]) =
                    *reinterpret_cast<const float4*>(&g_v[base + it * 4]);
            }
        }
        __syncthreads();

        // ---- S = Q K^T : 8x8 micro-tile, k-col pairs packed ----
        ull s2[8][4];
#pragma unroll
        for (int i = 0; i < 8; i++)
#pragma unroll
            for (int jp = 0; jp < 4; jp++) s2[i][jp] = 0ull;

#pragma unroll
        for (int h0 = 0; h0 < HDIM; h0 += 4) {
            float4 qf[8];
#pragma unroll
            for (int i = 0; i < 8; i++)
                qf[i] = *reinterpret_cast<const float4*>(&Qs[(ty * 8 + i) * HP + h0]);
#pragma unroll
            for (int hh = 0; hh < 4; hh++) {
                const ulonglong2 ka = *reinterpret_cast<const ulonglong2*>(
                    &KTs[(h0 + hh) * KP + tx * 8]);
                const ulonglong2 kb = *reinterpret_cast<const ulonglong2*>(
                    &KTs[(h0 + hh) * KP + tx * 8 + 4]);
#pragma unroll
                for (int i = 0; i < 8; i++) {
                    float qv = reinterpret_cast<const float*>(&qf[i])[hh];
                    ull qd = dup2(qv);
                    s2[i][0] = ffma2(qd, ka.x, s2[i][0]);
                    s2[i][1] = ffma2(qd, ka.y, s2[i][1]);
                    s2[i][2] = ffma2(qd, kb.x, s2[i][2]);
                    s2[i][3] = ffma2(qd, kb.y, s2[i][3]);
                }
            }
        }

        // ---- scale + causal mask + online softmax ----
        const bool diag = (kt == qt);
        float sf[8][8];
#pragma unroll
        for (int i = 0; i < 8; i++)
#pragma unroll
            for (int jp = 0; jp < 4; jp++)
                unpack2(s2[i][jp], sf[i][2 * jp], sf[i][2 * jp + 1]);

#pragma unroll
        for (int i = 0; i < 8; i++) {
            const int qrow = ty * 8 + i;
            float rm = -CUDART_INF_F;
#pragma unroll
            for (int j = 0; j < 8; j++) {
                float v = sf[i][j] * SCALE;
                if (diag && (tx * 8 + j) > qrow) v = -1e30f;
                sf[i][j] = v;
                rm = fmaxf(rm, v);
            }
#pragma unroll
            for (int d = 8; d > 0; d >>= 1)
                rm = fmaxf(rm, __shfl_xor_sync(0xffffffffu, rm, d));
            float mn = fmaxf(m[i], rm);
            float fc = __expf(m[i] - mn);
            float rs = 0.f;
#pragma unroll
            for (int j = 0; j < 8; j++) {
                float p = __expf(sf[i][j] - mn);
                sf[i][j] = p;
                rs += p;
            }
#pragma unroll
            for (int d = 8; d > 0; d >>= 1)
                rs += __shfl_xor_sync(0xffffffffu, rs, d);
            l[i] = l[i] * fc + rs;
            m[i] = mn;
            ull f2 = dup2(fc);
            o2[i][0] = fmul2(o2[i][0], f2);
            o2[i][1] = fmul2(o2[i][1], f2);
        }

        // write P tile
#pragma unroll
        for (int i = 0; i < 8; i++) {
            float* pr = &Ps[(ty * 8 + i) * KP + tx * 8];
            *reinterpret_cast<float4*>(pr) =
                make_float4(sf[i][0], sf[i][1], sf[i][2], sf[i][3]);
            *reinterpret_cast<float4*>(pr + 4) =
                make_float4(sf[i][4], sf[i][5], sf[i][6], sf[i][7]);
        }
        __syncthreads();

        // ---- O += P V : 8q x 4h per thread ----
#pragma unroll
        for (int k0 = 0; k0 < 128; k0 += 4) {
            float4 pf[8];
#pragma unroll
            for (int i = 0; i < 8; i++)
                pf[i] = *reinterpret_cast<const float4*>(&Ps[(ty * 8 + i) * KP + k0]);
#pragma unroll
            for (int kk = 0; kk < 4; kk++) {
                const ull va = *reinterpret_cast<const ull*>(&Vs[(k0 + kk) * HP + tx * 4]);
                const ull vb = *reinterpret_cast<const ull*>(&Vs[(k0 + kk) * HP + tx * 4 + 2]);
#pragma unroll
                for (int i = 0; i < 8; i++) {
                    float pv = reinterpret_cast<const float*>(&pf[i])[kk];
                    ull pd = dup2(pv);
                    o2[i][0] = ffma2(pd, va, o2[i][0]);
                    o2[i][1] = ffma2(pd, vb, o2[i][1]);
                }
            }
        }
    }

    // ---- epilogue: normalize, end-token row mask, store ----
    const int limit = g_limit[b];
    const float qnan = __int_as_float(0x7FC00000);
#pragma unroll
    for (int i = 0; i < 8; i++) {
        int q = q0 + ty * 8 + i;
        float4 r;
        if (q >= limit) {
            r = make_float4(qnan, qnan, qnan, qnan);
        } else {
            float inv = 1.f / l[i];
            float a0, a1, a2, a3;
            unpack2(o2[i][0], a0, a1);
            unpack2(o2[i][1], a2, a3);
            r = make_float4(a0 * inv, a1 * inv, a2 * inv, a3 * inv);
        }
        *reinterpret_cast<float4*>(&out[((size_t)b * SEQ + q) * HDIM + tx * 4]) = r;
    }
}

// ---------------------------------------------------------------------------
extern "C" void kernel_launch(void* const* d_in, const int* in_sizes, int n_in,
                              void* d_out, int out_size)
{
    const float* x  = (const float*)d_in[0];
    const float* Wk = (const float*)d_in[1];
    const float* Wq = (const float*)d_in[2];
    const float* Wv = (const float*)d_in[3];
    const int*  idx = (const int*)d_in[4];
    float* out = (float*)d_out;

    (void)in_sizes; (void)n_in; (void)out_size;

    cudaFuncSetAttribute(attn_kernel,
                         cudaFuncAttributeMaxDynamicSharedMemorySize,
                         ATTN_SMEM_BYTES);

    proj_kernel<<<ROWS_TOTAL / 64, 256>>>(x, Wk, Wq, Wv);
    limit_kernel<<<BATCH, 256>>>(idx);
    attn_kernel<<<dim3(SEQ / 128, BATCH), 256, ATTN_SMEM_BYTES>>>(out);
}

// round 6
// speedup vs baseline: 1.8959x; 1.8547x over previous
#include <cuda_runtime.h>
#include <cuda_bf16.h>
#include <math_constants.h>
#include <cstdint>

// Problem shape (fixed): B=16, T=2048, C=512, H=64
#define BATCH 16
#define SEQ   2048
#define CDIM  512
#define HDIM  64
#define END_TOKEN 32000

#define ROWS_TOTAL (BATCH * SEQ)          // 32768
#define SCALE 0.04419417382415922f        // 512^-0.5

__device__ __forceinline__ float tf32r(float x) {
    float y; asm("cvt.rna.tf32.f32 %0,%1;" : "=f"(y) : "f"(x)); return y;
}

// m16n8k8 tf32 mma (sm_80 portable feature -> fallback HMMA on sm_103)
__device__ __forceinline__ void mma_tf32(float* d, const uint32_t* a, const uint32_t* b) {
    asm volatile(
        "mma.sync.aligned.m16n8k8.row.col.f32.tf32.tf32.f32 "
        "{%0,%1,%2,%3}, {%4,%5,%6,%7}, {%8,%9}, {%0,%1,%2,%3};"
        : "+f"(d[0]), "+f"(d[1]), "+f"(d[2]), "+f"(d[3])
        : "r"(a[0]), "r"(a[1]), "r"(a[2]), "r"(a[3]), "r"(b[0]), "r"(b[1]));
}

// Scratch (allocation-free rule: __device__ globals)
__device__ float g_q[ROWS_TOTAL * HDIM];
__device__ float g_k[ROWS_TOTAL * HDIM];
__device__ float g_v[ROWS_TOTAL * HDIM];
__device__ float g_wt[3 * HDIM * CDIM];   // W^T, tf32-rounded: [mat][n][k]
__device__ int   g_limit[BATCH];

// ---------------------------------------------------------------------------
// Kernel 0: transpose W -> g_wt[m][n][k] (K-major) with tf32 rounding.
// ---------------------------------------------------------------------------
__global__ void transpose_w_kernel(const float* __restrict__ Wk,
                                   const float* __restrict__ Wq,
                                   const float* __restrict__ Wv)
{
    const int m  = blockIdx.x / 16;
    const int ks = blockIdx.x % 16;           // k-slice of 32
    const float* src = (m == 0) ? Wq : (m == 1) ? Wk : Wv;
    float* dst = g_wt + (size_t)m * HDIM * CDIM;
    for (int i = threadIdx.x; i < 32 * 64; i += 256) {
        int k = ks * 32 + (i >> 6);
        int n = i & 63;
        dst[(size_t)n * CDIM + k] = tf32r(src[(size_t)k * HDIM + n]);
    }
}

// ---------------------------------------------------------------------------
// Kernel 1: QKV projection via tf32 mma.sync.
// CTA: 64 rows x 192 cols (Q|K|V). 8 warps = 2(M) x 4(N); warp tile 32x48.
// K staged in 32-chunks; smem pad 36 -> conflict-free quad fragment loads.
// ---------------------------------------------------------------------------
__global__ __launch_bounds__(256) void proj_kernel(const float* __restrict__ x)
{
    __shared__ float As[64][36];
    __shared__ float Bs[192][36];

    const int t    = threadIdx.x;
    const int wid  = t >> 5;
    const int lane = t & 31;
    const int g    = lane >> 2;    // group id (row within 8)
    const int ctg  = lane & 3;     // thread-in-group (k within 4)
    const int wm   = wid >> 2;     // 0..1
    const int wn   = wid & 3;      // 0..3
    const int row0 = blockIdx.x * 64;

    float acc[2][6][4];
#pragma unroll
    for (int mt = 0; mt < 2; mt++)
#pragma unroll
        for (int nt = 0; nt < 6; nt++)
#pragma unroll
            for (int i = 0; i < 4; i++) acc[mt][nt][i] = 0.f;

    for (int kc = 0; kc < 16; kc++) {
        // stage A: 64 rows x 32, tf32-rounded
        {
            int r = t >> 2, f = (t & 3) * 8;
            const float* xp = x + (size_t)(row0 + r) * CDIM + kc * 32 + f;
            float4 u = *reinterpret_cast<const float4*>(xp);
            float4 v = *reinterpret_cast<const float4*>(xp + 4);
            As[r][f + 0] = tf32r(u.x); As[r][f + 1] = tf32r(u.y);
            As[r][f + 2] = tf32r(u.z); As[r][f + 3] = tf32r(u.w);
            As[r][f + 4] = tf32r(v.x); As[r][f + 5] = tf32r(v.y);
            As[r][f + 6] = tf32r(v.z); As[r][f + 7] = tf32r(v.w);
        }
        // stage B: 192 rows x 32 (pre-rounded)
#pragma unroll
        for (int i = 0; i < 3; i++) {
            int u  = t + 256 * i;
            int r  = u >> 2, f = (u & 3) * 8;
            const float* wp = g_wt + (size_t)r * CDIM + kc * 32 + f;
            float4 a = *reinterpret_cast<const float4*>(wp);
            float4 bx = *reinterpret_cast<const float4*>(wp + 4);
            *reinterpret_cast<float4*>(&Bs[r][f])     = a;
            *reinterpret_cast<float4*>(&Bs[r][f + 4]) = bx;
        }
        __syncthreads();

#pragma unroll
        for (int ks = 0; ks < 4; ks++) {
            const int kb = ks * 8;
            uint32_t a[2][4];
#pragma unroll
            for (int mt = 0; mt < 2; mt++) {
                int row = wm * 32 + mt * 16;
                a[mt][0] = __float_as_uint(As[row + g][kb + ctg]);
                a[mt][1] = __float_as_uint(As[row + g + 8][kb + ctg]);
                a[mt][2] = __float_as_uint(As[row + g][kb + ctg + 4]);
                a[mt][3] = __float_as_uint(As[row + g + 8][kb + ctg + 4]);
            }
            uint32_t b[6][2];
#pragma unroll
            for (int nt = 0; nt < 6; nt++) {
                int n = wn * 48 + nt * 8;
                b[nt][0] = __float_as_uint(Bs[n + g][kb + ctg]);
                b[nt][1] = __float_as_uint(Bs[n + g][kb + ctg + 4]);
            }
#pragma unroll
            for (int mt = 0; mt < 2; mt++)
#pragma unroll
                for (int nt = 0; nt < 6; nt++)
                    mma_tf32(acc[mt][nt], a[mt], b[nt]);
        }
        __syncthreads();
    }

    // epilogue
    float* outp[3] = { g_q, g_k, g_v };
#pragma unroll
    for (int mt = 0; mt < 2; mt++) {
#pragma unroll
        for (int nt = 0; nt < 6; nt++) {
            int col = wn * 48 + nt * 8 + 2 * ctg;
            int mat = col >> 6, cc = col & 63;
            int r0 = row0 + wm * 32 + mt * 16 + g;
            *reinterpret_cast<float2*>(outp[mat] + (size_t)r0 * HDIM + cc) =
                make_float2(acc[mt][nt][0], acc[mt][nt][1]);
            *reinterpret_cast<float2*>(outp[mat] + (size_t)(r0 + 8) * HDIM + cc) =
                make_float2(acc[mt][nt][2], acc[mt][nt][3]);
        }
    }
}

// ---------------------------------------------------------------------------
// Kernel 2: end-token scan per batch (faithful; never fires for this dataset).
// ---------------------------------------------------------------------------
__global__ void limit_kernel(const int* __restrict__ idx)
{
    __shared__ int best;
    if (threadIdx.x == 0) best = SEQ;
    __syncthreads();
    const int b = blockIdx.x;
    for (int t = threadIdx.x; t < SEQ; t += blockDim.x)
        if (idx[(size_t)b * SEQ + t] == END_TOKEN) atomicMin(&best, t);
    __syncthreads();
    if (threadIdx.x == 0) g_limit[b] = best;
}

// ---------------------------------------------------------------------------
// Kernel 3: causal flash attention via tf32 mma.sync.
// Tile 128q x 128k. 8 warps, each owns 16 q-rows (full 128 k-cols for S),
// so softmax row reductions are quad-shuffles only.
// smem (floats): Qs[128][68], Ks[128][68] ([k][h]), VT[64][132] ([h][k]),
//                Ps[128][132]. Total 171,008 B -> 1 CTA/SM.
// ---------------------------------------------------------------------------
#define QP 68
#define VP 132
#define OFF_KS (128 * QP)
#define OFF_VT (OFF_KS + 128 * QP)
#define OFF_PS (OFF_VT + 64 * VP)
#define ATTN_SMEM_FLOATS (OFF_PS + 128 * VP)
#define ATTN_SMEM_BYTES (ATTN_SMEM_FLOATS * 4)

__global__ __launch_bounds__(256, 1) void attn_kernel(float* __restrict__ out)
{
    extern __shared__ float smf[];
    float* Qs = smf;            // [128][QP]  [q][h]
    float* Ks = smf + OFF_KS;   // [128][QP]  [k][h]
    float* VT = smf + OFF_VT;   // [64][VP]   [h][k]
    float* Ps = smf + OFF_PS;   // [128][VP]  [q][k]

    const int t    = threadIdx.x;
    const int wid  = t >> 5;
    const int lane = t & 31;
    const int g    = lane >> 2;
    const int ctg  = lane & 3;
    const int qw   = wid * 16;              // warp's q-row base in tile
    const int b    = blockIdx.y;
    const int qt   = (gridDim.x - 1) - blockIdx.x;   // heavy tiles first
    const int q0   = qt * 128;

    // stage Q (tf32-rounded)
    {
        int r = t >> 1, f0 = (t & 1) * 32;
        const float* qp = g_q + ((size_t)b * SEQ + q0 + r) * HDIM + f0;
#pragma unroll
        for (int it = 0; it < 8; it++) {
            float4 v = *reinterpret_cast<const float4*>(qp + it * 4);
            v.x = tf32r(v.x); v.y = tf32r(v.y); v.z = tf32r(v.z); v.w = tf32r(v.w);
            *reinterpret_cast<float4*>(&Qs[r * QP + f0 + it * 4]) = v;
        }
    }

    float mrow[2] = { -CUDART_INF_F, -CUDART_INF_F };
    float lrow[2] = { 0.f, 0.f };
    float o[8][4];
#pragma unroll
    for (int nt = 0; nt < 8; nt++)
#pragma unroll
        for (int i = 0; i < 4; i++) o[nt][i] = 0.f;

    for (int kt = 0; kt <= qt; kt++) {
        __syncthreads();   // prior-iter smem reads done (also covers Q staging)

        // stage K [k][h] (rounded) and V transposed [h][k] (rounded)
        {
            int r = t >> 1, f0 = (t & 1) * 32;
            const size_t base = ((size_t)b * SEQ + kt * 128 + r) * HDIM + f0;
#pragma unroll
            for (int it = 0; it < 8; it++) {
                float4 kv = *reinterpret_cast<const float4*>(&g_k[base + it * 4]);
                kv.x = tf32r(kv.x); kv.y = tf32r(kv.y);
                kv.z = tf32r(kv.z); kv.w = tf32r(kv.w);
                *reinterpret_cast<float4*>(&Ks[r * QP + f0 + it * 4]) = kv;
                float4 vv = *reinterpret_cast<const float4*>(&g_v[base + it * 4]);
                int h = f0 + it * 4;
                VT[(h + 0) * VP + r] = tf32r(vv.x);
                VT[(h + 1) * VP + r] = tf32r(vv.y);
                VT[(h + 2) * VP + r] = tf32r(vv.z);
                VT[(h + 3) * VP + r] = tf32r(vv.w);
            }
        }
        __syncthreads();

        // ---- S = Q K^T : warp tile 16 x 128, 16 n-tiles ----
        float s[16][4];
#pragma unroll
        for (int nt = 0; nt < 16; nt++)
#pragma unroll
            for (int i = 0; i < 4; i++) s[nt][i] = 0.f;

#pragma unroll
        for (int ks = 0; ks < 8; ks++) {
            const int kb = ks * 8;
            uint32_t a[4];
            a[0] = __float_as_uint(Qs[(qw + g) * QP + kb + ctg]);
            a[1] = __float_as_uint(Qs[(qw + g + 8) * QP + kb + ctg]);
            a[2] = __float_as_uint(Qs[(qw + g) * QP + kb + ctg + 4]);
            a[3] = __float_as_uint(Qs[(qw + g + 8) * QP + kb + ctg + 4]);
#pragma unroll
            for (int nt = 0; nt < 16; nt++) {
                uint32_t bb[2];
                bb[0] = __float_as_uint(Ks[(nt * 8 + g) * QP + kb + ctg]);
                bb[1] = __float_as_uint(Ks[(nt * 8 + g) * QP + kb + ctg + 4]);
                mma_tf32(s[nt], a, bb);
            }
        }

        // ---- scale + causal mask + online softmax (rows g, g+8) ----
        const bool diag = (kt == qt);
        const int r0l = qw + g, r1l = r0l + 8;   // local q rows
        float rm0 = -CUDART_INF_F, rm1 = -CUDART_INF_F;
#pragma unroll
        for (int nt = 0; nt < 16; nt++) {
            int cl = nt * 8 + 2 * ctg;
#pragma unroll
            for (int c = 0; c < 2; c++) {
                float v0 = s[nt][c] * SCALE;
                float v1 = s[nt][2 + c] * SCALE;
                if (diag) {
                    if (cl + c > r0l) v0 = -1e30f;
                    if (cl + c > r1l) v1 = -1e30f;
                }
                s[nt][c] = v0; s[nt][2 + c] = v1;
                rm0 = fmaxf(rm0, v0); rm1 = fmaxf(rm1, v1);
            }
        }
        rm0 = fmaxf(rm0, __shfl_xor_sync(0xffffffffu, rm0, 1));
        rm0 = fmaxf(rm0, __shfl_xor_sync(0xffffffffu, rm0, 2));
        rm1 = fmaxf(rm1, __shfl_xor_sync(0xffffffffu, rm1, 1));
        rm1 = fmaxf(rm1, __shfl_xor_sync(0xffffffffu, rm1, 2));

        float mn0 = fmaxf(mrow[0], rm0), mn1 = fmaxf(mrow[1], rm1);
        float fc0 = __expf(mrow[0] - mn0), fc1 = __expf(mrow[1] - mn1);
        float rs0 = 0.f, rs1 = 0.f;
#pragma unroll
        for (int nt = 0; nt < 16; nt++) {
#pragma unroll
            for (int c = 0; c < 2; c++) {
                float p0 = __expf(s[nt][c] - mn0);
                float p1 = __expf(s[nt][2 + c] - mn1);
                s[nt][c] = p0; s[nt][2 + c] = p1;
                rs0 += p0; rs1 += p1;
            }
        }
        rs0 += __shfl_xor_sync(0xffffffffu, rs0, 1);
        rs0 += __shfl_xor_sync(0xffffffffu, rs0, 2);
        rs1 += __shfl_xor_sync(0xffffffffu, rs1, 1);
        rs1 += __shfl_xor_sync(0xffffffffu, rs1, 2);

        lrow[0] = lrow[0] * fc0 + rs0;
        lrow[1] = lrow[1] * fc1 + rs1;
        mrow[0] = mn0; mrow[1] = mn1;
#pragma unroll
        for (int nt = 0; nt < 8; nt++) {
            o[nt][0] *= fc0; o[nt][1] *= fc0;
            o[nt][2] *= fc1; o[nt][3] *= fc1;
        }

        // ---- write P tile to smem ----
#pragma unroll
        for (int nt = 0; nt < 16; nt++) {
            int cl = nt * 8 + 2 * ctg;
            *reinterpret_cast<float2*>(&Ps[(qw + g) * VP + cl]) =
                make_float2(s[nt][0], s[nt][1]);
            *reinterpret_cast<float2*>(&Ps[(qw + g + 8) * VP + cl]) =
                make_float2(s[nt][2], s[nt][3]);
        }
        __syncthreads();

        // ---- O += P V : warp tile 16 x 64, K=128 (16 k-steps) ----
#pragma unroll
        for (int ks = 0; ks < 16; ks++) {
            const int kb = ks * 8;
            uint32_t a[4];
            a[0] = __float_as_uint(Ps[(qw + g) * VP + kb + ctg]);
            a[1] = __float_as_uint(Ps[(qw + g + 8) * VP + kb + ctg]);
            a[2] = __float_as_uint(Ps[(qw + g) * VP + kb + ctg + 4]);
            a[3] = __float_as_uint(Ps[(qw + g + 8) * VP + kb + ctg + 4]);
#pragma unroll
            for (int nt = 0; nt < 8; nt++) {
                uint32_t bb[2];
                bb[0] = __float_as_uint(VT[(nt * 8 + g) * VP + kb + ctg]);
                bb[1] = __float_as_uint(VT[(nt * 8 + g) * VP + kb + ctg + 4]);
                mma_tf32(o[nt], a, bb);
            }
        }
    }

    // ---- epilogue: normalize, end-token row mask, store ----
    const int limit = g_limit[b];
    const float qnan = __int_as_float(0x7FC00000);
    const int q0g = q0 + qw + g;
    const float inv0 = 1.f / lrow[0];
    const float inv1 = 1.f / lrow[1];
#pragma unroll
    for (int nt = 0; nt < 8; nt++) {
        int col = nt * 8 + 2 * ctg;
        float2 r0v, r1v;
        if (q0g >= limit) r0v = make_float2(qnan, qnan);
        else r0v = make_float2(o[nt][0] * inv0, o[nt][1] * inv0);
        if (q0g + 8 >= limit) r1v = make_float2(qnan, qnan);
        else r1v = make_float2(o[nt][2] * inv1, o[nt][3] * inv1);
        *reinterpret_cast<float2*>(&out[((size_t)b * SEQ + q0g) * HDIM + col]) = r0v;
        *reinterpret_cast<float2*>(&out[((size_t)b * SEQ + q0g + 8) * HDIM + col]) = r1v;
    }
}

// ---------------------------------------------------------------------------
extern "C" void kernel_launch(void* const* d_in, const int* in_sizes, int n_in,
                              void* d_out, int out_size)
{
    const float* x  = (const float*)d_in[0];
    const float* Wk = (const float*)d_in[1];
    const float* Wq = (const float*)d_in[2];
    const float* Wv = (const float*)d_in[3];
    const int*  idx = (const int*)d_in[4];
    float* out = (float*)d_out;

    (void)in_sizes; (void)n_in; (void)out_size;

    cudaFuncSetAttribute(attn_kernel,
                         cudaFuncAttributeMaxDynamicSharedMemorySize,
                         ATTN_SMEM_BYTES);

    transpose_w_kernel<<<48, 256>>>(Wk, Wq, Wv);
    proj_kernel<<<ROWS_TOTAL / 64, 256>>>(x);
    limit_kernel<<<BATCH, 256>>>(idx);
    attn_kernel<<<dim3(SEQ / 128, BATCH), 256, ATTN_SMEM_BYTES>>>(out);
}